// round 10
// baseline (speedup 1.0000x reference)
#include <cuda_runtime.h>
#include <cuda_fp16.h>
#include <cstdint>

#define N_NODES 2048
#define F_DIM   128
#define UNITS   128
#define FE_DIM  16
#define DEG     64
#define N_EDGES (N_NODES * DEG)

__device__ __half g_hr[N_NODES * UNITS];   // fp16: halves aggregation traffic
__device__ float  g_al[N_NODES];
__device__ float  g_ar[N_NODES];
__device__ float  g_dot[N_EDGES];          // precomputed ef[src,dst] . wev

__device__ __forceinline__ float lrelu(float x) {
    return x > 0.0f ? x : 0.2f * x;
}

// Packed f32x2 (PTX-only; numerics = two IEEE fma.rn)
__device__ __forceinline__ unsigned long long pack2(float lo, float hi) {
    unsigned long long r;
    asm("mov.b64 %0, {%1, %2};" : "=l"(r) : "f"(lo), "f"(hi));
    return r;
}
__device__ __forceinline__ void unpack2(float& lo, float& hi, unsigned long long v) {
    asm("mov.b64 {%0, %1}, %2;" : "=f"(lo), "=f"(hi) : "l"(v));
}
__device__ __forceinline__ void fma2(unsigned long long& d,
                                     unsigned long long a,
                                     unsigned long long b) {
    asm("fma.rn.f32x2 %0, %1, %2, %3;" : "=l"(d) : "l"(a), "l"(b), "l"(d));
}

// Kernel A: 1536 blocks x 128 threads.
//   blocks [0,512):    side-split GEMM (R8 body): L->al, R->g_hr(fp16)+ar
//   blocks [512,1536): ef gather + dot: 128 edges/block -> g_dot
// The DRAM-latency-heavy gather overlaps the FMA-heavy gemm.
#define NPB   8
#define NSPAD 12
#define GEMM_GRID 512
__global__ __launch_bounds__(128)
void prep_kernel(const float* __restrict__ ns,
                 const int* __restrict__ edges,
                 const float* __restrict__ ef,
                 const float* __restrict__ Wl,
                 const float* __restrict__ Wr,
                 const float* __restrict__ W_attn,
                 const float* __restrict__ W_edge) {
    const int b = blockIdx.x;
    const int t = threadIdx.x;
    const int w = t >> 5, lane = t & 31;

    if (b >= GEMM_GRID) {
        // -------- dot blocks: 128 edges (2 nodes) per block --------
        __shared__ float s_wev[FE_DIM];
        if (t < FE_DIM) {
            float s = 0.0f;
            #pragma unroll
            for (int j = 0; j < FE_DIM; j++)
                s += W_edge[t * FE_DIM + j] * W_attn[2 * UNITS + j];
            s_wev[t] = s;
        }
        __syncthreads();

        const int e   = (b - GEMM_GRID) * 128 + t;
        const int src = e >> 6;                       // src == repeat(arange)
        const int dst = edges[2 * e + 1];
        const float4* p = reinterpret_cast<const float4*>(
            ef + ((size_t)src * N_NODES + (size_t)dst) * FE_DIM);
        float dot = 0.0f;
        #pragma unroll
        for (int i = 0; i < 4; i++) {
            const float4 v = p[i];
            dot = fmaf(v.x, s_wev[4 * i + 0], dot);
            dot = fmaf(v.y, s_wev[4 * i + 1], dot);
            dot = fmaf(v.z, s_wev[4 * i + 2], dot);
            dot = fmaf(v.w, s_wev[4 * i + 3], dot);
        }
        g_dot[e] = dot;                               // coalesced store
        return;
    }

    // -------- gemm blocks (R8/R9 body) --------
    const int side = b >> 8;               // 0 = L, 1 = R
    const int n0   = (b & 255) * NPB;

    __shared__ float s_ns[F_DIM][NSPAD];   // [k][node]
    #pragma unroll
    for (int j = 0; j < NPB; j++)
        s_ns[t][j] = ns[(n0 + j) * F_DIM + t];
    __syncthreads();

    const float* __restrict__ W = side ? Wr : Wl;

    unsigned long long acc[4];             // acc[j] = (h_{2j}, h_{2j+1})
    #pragma unroll
    for (int j = 0; j < 4; j++) acc[j] = 0ull;

    #pragma unroll 8
    for (int k = 0; k < F_DIM; k++) {
        const float wv = W[k * UNITS + t];           // coalesced, L1-cached
        const unsigned long long wp = pack2(wv, wv);
        const ulonglong2* row = reinterpret_cast<const ulonglong2*>(&s_ns[k][0]);
        const ulonglong2 r0 = row[0];
        const ulonglong2 r1 = row[1];
        fma2(acc[0], r0.x, wp);
        fma2(acc[1], r0.y, wp);
        fma2(acc[2], r1.x, wp);
        fma2(acc[3], r1.y, wp);
    }

    float h[NPB];
    #pragma unroll
    for (int j = 0; j < 4; j++) unpack2(h[2 * j], h[2 * j + 1], acc[j]);

    if (side) {
        #pragma unroll
        for (int j = 0; j < NPB; j++)
            g_hr[(n0 + j) * UNITS + t] = __float2half_rn(h[j]);
    }

    const float wa = W_attn[side * UNITS + t];
    __shared__ float s_red[NPB][4];
    #pragma unroll
    for (int j = 0; j < NPB; j++) {
        float p = lrelu(h[j]) * wa;
        #pragma unroll
        for (int o = 16; o > 0; o >>= 1)
            p += __shfl_down_sync(0xffffffffu, p, o);
        if (lane == 0) s_red[j][w] = p;
    }
    __syncthreads();
    if (t < NPB) {
        float* dstv = side ? g_ar : g_al;
        dstv[n0 + t] = s_red[t][0] + s_red[t][1] + s_red[t][2] + s_red[t][3];
    }
}

// Kernel B: R9 shape (grid 2048, 1 node/block, 128 threads); score phase
// reads precomputed g_dot (coalesced, L2) instead of gathering ef from DRAM.
__global__ __launch_bounds__(128)
void attn_kernel(const int* __restrict__ edges,
                 float* __restrict__ out) {
    const int n = blockIdx.x;
    const int t = threadIdx.x;
    const int w = t >> 5, lane = t & 31;

    __shared__ float s_score[DEG];
    __shared__ int   s_dst[DEG];
    __shared__ float s_acc[4][UNITS];
    __shared__ float s_part[2];
    __shared__ float s_inv;

    if (t < DEG) {
        const int e   = n * DEG + t;
        const int dst = edges[2 * e + 1];
        float s = g_al[n] + g_ar[dst] + g_dot[e];
        s = fminf(2.0f, fmaxf(-2.0f, s));
        const float sc = __expf(s);
        s_score[t] = sc;
        s_dst[t]   = dst;

        float v = sc;
        #pragma unroll
        for (int o = 16; o > 0; o >>= 1)
            v += __shfl_down_sync(0xffffffffu, v, o);
        if (lane == 0) s_part[t >> 5] = v;
    }
    __syncthreads();
    if (t == 0) s_inv = 1.0f / (s_part[0] + s_part[1]);

    // aggregation: warp w -> edges [w*16, +16). Half-warp per edge; lane
    // loads 8 halves (16B LDG.128) of the fp16 hr row; fp32 accumulators.
    const int ebase = w * 16;
    const int sub   = lane >> 4;
    const int c0    = (lane & 15) * 8;

    float acc[8];
    #pragma unroll
    for (int k = 0; k < 8; k++) acc[k] = 0.0f;

    #pragma unroll
    for (int i = 0; i < 8; i++) {
        const int e = ebase + 2 * i + sub;
        const float sc = s_score[e];
        const int4 hv = *reinterpret_cast<const int4*>(
            g_hr + s_dst[e] * UNITS + c0);
        const __half2* hp = reinterpret_cast<const __half2*>(&hv);
        #pragma unroll
        for (int k = 0; k < 4; k++) {
            const float2 f = __half22float2(hp[k]);
            acc[2 * k]     = fmaf(sc, f.x, acc[2 * k]);
            acc[2 * k + 1] = fmaf(sc, f.y, acc[2 * k + 1]);
        }
    }
    #pragma unroll
    for (int k = 0; k < 8; k++)
        acc[k] += __shfl_down_sync(0xffffffffu, acc[k], 16);

    if (lane < 16) {
        *reinterpret_cast<float4*>(&s_acc[w][c0]) =
            make_float4(acc[0], acc[1], acc[2], acc[3]);
        *reinterpret_cast<float4*>(&s_acc[w][c0 + 4]) =
            make_float4(acc[4], acc[5], acc[6], acc[7]);
    }
    __syncthreads();   // also publishes s_inv

    out[n * UNITS + t] =
        (s_acc[0][t] + s_acc[1][t] + s_acc[2][t] + s_acc[3][t]) * s_inv;
}

extern "C" void kernel_launch(void* const* d_in, const int* in_sizes, int n_in,
                              void* d_out, int out_size) {
    const float* ns      = (const float*)d_in[0];
    const int*   edges   = (const int*)d_in[1];
    const float* ef      = (const float*)d_in[2];
    const float* W_left  = (const float*)d_in[3];
    const float* W_right = (const float*)d_in[4];
    const float* W_attn  = (const float*)d_in[5];
    const float* W_edge  = (const float*)d_in[6];
    float* out = (float*)d_out;

    prep_kernel<<<GEMM_GRID + N_EDGES / 128, 128>>>(
        ns, edges, ef, W_left, W_right, W_attn, W_edge);
    attn_kernel<<<N_NODES, 128>>>(edges, out);
}